// round 11
// baseline (speedup 1.0000x reference)
#include <cuda_runtime.h>
#include <cuda_bf16.h>

// Problem constants
#define B 4
#define P 12000
#define C 64
#define H 512
#define W 512
#define TILE_X 128
#define SLOT_CAP 20      // staged rows per tile (mean occ 5.9; +6 sigma)
#define PAD 68           // s_feat row stride (floats); 272B keeps 16B alignment
#define NT 8192          // total tiles
#define NBLK 2048        // persistent blocks, exactly 4 tiles each, single wave
#define TPB 128

// Winner pillar map per output pixel, encoded as (p+1); 0 = empty.
// Zero-initialized at module load; gather restores every strip to 0
// (read-then-clear by the SAME thread => ordered), so the all-zeros
// invariant holds before every kernel_launch call / graph replay.
__device__ int g_winner[B * H * W];

// Kernel 1: one thread per (b, p). Reference semantics: sequential .at[].set
// means the LARGEST pillar index wins per pixel -> atomicMax on (p+1).
__global__ void scatter_winner_kernel(const int* __restrict__ coords) {
    int i = blockIdx.x * blockDim.x + threadIdx.x;   // i = b*P + p
    if (i >= B * P) return;
    int b = i / P;
    int p = i - b * P;
    int4 c4 = reinterpret_cast<const int4*>(coords)[i];  // (batch, y, x, z)
    int y = c4.y;
    int x = c4.z;
    if ((unsigned)x < (unsigned)W && (unsigned)y < (unsigned)H) {
        atomicMax(&g_winner[(b * H + y) * W + x], p + 1);
    }
}

__device__ __forceinline__ void cp16(float* smem_dst, const float4* gsrc) {
    unsigned sa = (unsigned)__cvta_generic_to_shared(smem_dst);
    asm volatile("cp.async.cg.shared.global [%0], [%1], 16;" :: "r"(sa), "l"(gsrc));
}
__device__ __forceinline__ void cp_commit() {
    asm volatile("cp.async.commit_group;" ::: "memory");
}
__device__ __forceinline__ void cp_wait0() {
    asm volatile("cp.async.wait_group 0;" ::: "memory");
}

// Kernel 2: persistent, software-pipelined. All 128 threads both produce
// (compact + cp.async-stage tile k+1, prefetch winner k+2 into a register)
// and emit (tile k store burst). Latency of all produce work drains under
// the emit burst; one pipeline fill per block total.
__global__ __launch_bounds__(TPB) void gather_out_kernel(
    const float* __restrict__ feat, float* __restrict__ out) {
    // 16B alignment REQUIRED: cp.async destination. Declare first.
    __shared__ __align__(16) float s_feat[2][SLOT_CAP * PAD];
    __shared__ int   s_slot[2][TILE_X];  // >=0: slot | -1: empty | <=-2: pid=-(s)-2
    __shared__ int   s_pid[2][SLOT_CAP];
    __shared__ int   s_n[2];
    __shared__ int   s_wcnt[4];
    __shared__ float s_zero[64];

    const int tid  = threadIdx.x;
    const int lane = tid & 31;
    const int wid  = tid >> 5;
    const unsigned lt = (1u << lane) - 1u;
    if (tid < 64) s_zero[tid] = 0.0f;

    // tile t -> b = t>>11, y = (t>>2)&511, xt = t&3

// Read one winner int per thread (coalesced 512B strip) and clear it.
// Same thread reads then writes the same address => hardware-ordered.
#define READ_CLEAR(TT, WDST)                                                  \
    do {                                                                      \
        const int t_ = (TT);                                                  \
        int* wr_ = g_winner + (((t_ >> 11) * H + ((t_ >> 2) & (H - 1))) * W)  \
                 + (t_ & 3) * TILE_X;                                         \
        (WDST) = wr_[tid];                                                    \
        wr_[tid] = 0;                                                         \
    } while (0)

// Compact winner regs into buffer BF (ballot + cross-warp prefix), then
// issue cp.async feature staging for tile TT into s_feat[BF]. No wait here.
#define COMPACT_STAGE(WV, BF, TT)                                             \
    do {                                                                      \
        const int t_ = (TT);                                                  \
        const bool occ_ = ((WV) > 0);                                         \
        const unsigned m_ = __ballot_sync(0xFFFFFFFFu, occ_);                 \
        if (lane == 0) s_wcnt[wid] = __popc(m_);                              \
        __syncthreads();                                                      \
        int base_ = 0;                                                        \
        if (wid > 0) base_ += s_wcnt[0];                                      \
        if (wid > 1) base_ += s_wcnt[1];                                      \
        if (wid > 2) base_ += s_wcnt[2];                                      \
        int s_ = -1;                                                          \
        if (occ_) {                                                           \
            int sl_ = base_ + __popc(m_ & lt);                                \
            if (sl_ < SLOT_CAP) { s_pid[BF][sl_] = (WV) - 1; s_ = sl_; }      \
            else                { s_ = -((WV) + 1); }  /* pid = -s - 2 */     \
        }                                                                     \
        s_slot[BF][tid] = s_;                                                 \
        if (tid == 96) s_n[BF] = base_ + __popc(m_);   /* wid3 lane0 */       \
        __syncthreads();                                                      \
        const int ns_ = min(s_n[BF], SLOT_CAP);                               \
        const float4* fb4_ = reinterpret_cast<const float4*>(feat)            \
                           + (size_t)(t_ >> 11) * P * (C / 4);                \
        for (int j = tid; j < ns_ * (C / 4); j += TPB) {                      \
            int sl_ = j >> 4;                                                 \
            int q_  = j & 15;                                                 \
            cp16(&s_feat[BF][sl_ * PAD + q_ * 4],                             \
                 &fb4_[(size_t)s_pid[BF][sl_] * (C / 4) + q_]);               \
        }                                                                     \
        cp_commit();                                                          \
    } while (0)

    const int bid = blockIdx.x;
    int w;

    // ---- pipeline fill ----
    READ_CLEAR(bid, w);
    COMPACT_STAGE(w, 0, bid);
    READ_CLEAR(bid + NBLK, w);
    cp_wait0();
    __syncthreads();

    int buf = 0;
    const size_t step = (size_t)4 * H * (W / 4);   // c += 4, in float4

    #pragma unroll
    for (int i = 0; i < 4; ++i) {
        const int t = bid + i * NBLK;

        // Produce tile i+1 (compaction is cheap ALU; cp.asyncs + winner LDG
        // are fire-and-forget, draining under the emit burst below).
        if (i < 3) {
            COMPACT_STAGE(w, buf ^ 1, t + NBLK);
            if (i < 2) READ_CLEAR(t + 2 * NBLK, w);
        }

        // ---- emit tile t from buffer buf ----
        {
            const int b  = t >> 11;
            const int y  = (t >> 2) & (H - 1);
            const int xt = t & 3;
            const int c0 = wid;           // 0..3
            const int px = lane * 4;      // lane = x-quad

            const int s0 = s_slot[buf][px + 0];
            const int s1 = s_slot[buf][px + 1];
            const int s2 = s_slot[buf][px + 2];
            const int s3 = s_slot[buf][px + 3];

            float4* dst = reinterpret_cast<float4*>(out)
                        + ((size_t)(b * C + c0) * H + y) * (W / 4)
                        + xt * (TILE_X / 4) + lane;

            if (s_n[buf] <= SLOT_CAP) {
                const float* fb = s_feat[buf];
                const float* f0 = (s0 >= 0) ? fb + s0 * PAD : s_zero;
                const float* f1 = (s1 >= 0) ? fb + s1 * PAD : s_zero;
                const float* f2 = (s2 >= 0) ? fb + s2 * PAD : s_zero;
                const float* f3 = (s3 >= 0) ? fb + s3 * PAD : s_zero;
                #pragma unroll 8
                for (int it = 0; it < 16; ++it) {
                    const int c = c0 + 4 * it;
                    float4 v = make_float4(f0[c], f1[c], f2[c], f3[c]);
                    __stcs(dst, v);
                    dst += step;
                }
            } else {
                // Statistically-never slow path (>SLOT_CAP occupied px).
                const float* featb = feat + (size_t)b * P * C;
                #pragma unroll 4
                for (int it = 0; it < 16; ++it) {
                    const int c = c0 + 4 * it;
                    float4 v;
                    v.x = (s0 >= 0) ? s_feat[buf][s0 * PAD + c]
                        : (s0 == -1) ? 0.0f : featb[(size_t)(-s0 - 2) * C + c];
                    v.y = (s1 >= 0) ? s_feat[buf][s1 * PAD + c]
                        : (s1 == -1) ? 0.0f : featb[(size_t)(-s1 - 2) * C + c];
                    v.z = (s2 >= 0) ? s_feat[buf][s2 * PAD + c]
                        : (s2 == -1) ? 0.0f : featb[(size_t)(-s2 - 2) * C + c];
                    v.w = (s3 >= 0) ? s_feat[buf][s3 * PAD + c]
                        : (s3 == -1) ? 0.0f : featb[(size_t)(-s3 - 2) * C + c];
                    __stcs(dst, v);
                    dst += step;
                }
            }
        }

        if (i < 3) { cp_wait0(); __syncthreads(); }
        buf ^= 1;
    }
#undef READ_CLEAR
#undef COMPACT_STAGE
}

extern "C" void kernel_launch(void* const* d_in, const int* in_sizes, int n_in,
                              void* d_out, int out_size) {
    const float* feat   = (const float*)d_in[0];   // [B, P, C] fp32
    const int*   coords = (const int*)d_in[1];     // [B, P, 4] int32
    float* out = (float*)d_out;                    // [B, C, H, W] fp32

    scatter_winner_kernel<<<(B * P + 255) / 256, 256>>>(coords);

    gather_out_kernel<<<NBLK, TPB>>>(feat, out);
}

// round 13
// speedup vs baseline: 1.0450x; 1.0450x over previous
#include <cuda_runtime.h>
#include <cuda_bf16.h>

// Problem constants
#define B 4
#define P 12000
#define C 64
#define H 512
#define W 512
#define TILE_X 128
#define SLOT_CAP 20   // staged rows per 128-px tile (mean occ 5.9; +6 sigma)

// Winner pillar map per output pixel, encoded as (p+1); 0 = empty.
// Zero-initialized at module load; gather restores every strip to 0
// (read-then-clear by the SAME thread => ordered), so the all-zeros
// invariant holds before every kernel_launch call / graph replay.
__device__ int g_winner[B * H * W];

// Kernel 1: one thread per (b, p). Reference semantics: sequential .at[].set
// means the LARGEST pillar index wins per pixel -> atomicMax on (p+1).
__global__ void scatter_winner_kernel(const int* __restrict__ coords) {
    int i = blockIdx.x * blockDim.x + threadIdx.x;   // i = b*P + p
    if (i >= B * P) return;
    int b = i / P;
    int p = i - b * P;
    int4 c4 = reinterpret_cast<const int4*>(coords)[i];  // (batch, y, x, z)
    int y = c4.y;
    int x = c4.z;
    if ((unsigned)x < (unsigned)W && (unsigned)y < (unsigned)H) {
        atomicMax(&g_winner[(b * H + y) * W + x], p + 1);
    }
}

// Kernel 2: one 128-thread block per (b, y, 128-px x-tile). 8192 blocks,
// 16 resident/SM (launch_bounds-capped regs), ~3.5 waves -> late-block
// prologues overlap early-block store streams (the proven mechanism).
// Ballot compaction: 1 barrier between winner load and staging, no atomics.
__global__ __launch_bounds__(128, 16) void gather_out_kernel(
    const float* __restrict__ feat, float* __restrict__ out) {
    __shared__ int   s_slot[TILE_X];   // >=0: slot | -1: empty | <=-2: pid=-(s)-2
    __shared__ int   s_pid[SLOT_CAP];
    __shared__ int   s_wcnt[4];
    __shared__ float s_feat[(SLOT_CAP + 1) * 65];  // +1 = zero row; pad 65

    const int b    = blockIdx.z;
    const int y    = blockIdx.y;
    const int x0   = blockIdx.x * TILE_X;
    const int tid  = threadIdx.x;
    const int lane = tid & 31;
    const int wid  = tid >> 5;
    const unsigned lt = (1u << lane) - 1u;

    // --- Phase 1: every thread reads+clears ONE winner (coalesced 512 B),
    //              ballot-compacts within its warp.
    int* wrow = g_winner + (b * H + y) * W + x0;
    const int wv = wrow[tid];
    wrow[tid] = 0;                       // same thread as reader => ordered

    const bool occ = (wv > 0);
    const unsigned m = __ballot_sync(0xFFFFFFFFu, occ);
    if (lane == 0) s_wcnt[wid] = __popc(m);
    if (tid >= 64 && tid < 64 + 65)      // zero row (between ballot & barrier)
        s_feat[SLOT_CAP * 65 + (tid - 64)] = 0.0f;
    __syncthreads();

    // cross-warp exclusive prefix of occupied counts
    int base = 0;
    if (wid > 0) base += s_wcnt[0];
    if (wid > 1) base += s_wcnt[1];
    if (wid > 2) base += s_wcnt[2];
    const int n_total = base + s_wcnt[3]
                      + ((wid == 3) ? 0 : 0);           // (uniform read below)
    const int n_all = s_wcnt[0] + s_wcnt[1] + s_wcnt[2] + s_wcnt[3];

    int s = -1;
    if (occ) {
        int sl = base + __popc(m & lt);
        if (sl < SLOT_CAP) { s_pid[sl] = wv - 1; s = sl; }
        else               { s = -(wv + 1); }            // pid = -s - 2
    }
    s_slot[tid] = s;
    __syncthreads();
    (void)n_total;

    // --- Phase 2: stage occupied feature rows (coalesced float4 loads).
    const float* featb = feat + (size_t)b * P * C;
    const float4* featb4 = reinterpret_cast<const float4*>(featb);
    const int n_stage = min(n_all, SLOT_CAP);
    for (int i = tid; i < n_stage * (C / 4); i += 128) {
        int sl = i >> 4;          // C/4 == 16
        int q  = i & 15;
        float4 v = __ldg(&featb4[(size_t)s_pid[sl] * (C / 4) + q]);
        float* dst = &s_feat[sl * 65 + q * 4];
        dst[0] = v.x; dst[1] = v.y; dst[2] = v.z; dst[3] = v.w;
    }
    __syncthreads();

    // --- Phase 3: emit. lane = x-quad (32 quads), warp w = channels w+4*it.
    const int c0 = wid;                  // 0..3
    const int px = lane * 4;

    const int s0 = s_slot[px + 0];
    const int s1 = s_slot[px + 1];
    const int s2 = s_slot[px + 2];
    const int s3 = s_slot[px + 3];

    float4* dst = reinterpret_cast<float4*>(out)
                + ((size_t)(b * C + c0) * H + y) * (W / 4) + (x0 / 4) + lane;
    const size_t step = (size_t)4 * H * (W / 4);   // c += 4

    if (n_all <= SLOT_CAP) {
        const float* f0 = s_feat + (s0 >= 0 ? s0 : SLOT_CAP) * 65;
        const float* f1 = s_feat + (s1 >= 0 ? s1 : SLOT_CAP) * 65;
        const float* f2 = s_feat + (s2 >= 0 ? s2 : SLOT_CAP) * 65;
        const float* f3 = s_feat + (s3 >= 0 ? s3 : SLOT_CAP) * 65;
        #pragma unroll 8
        for (int it = 0; it < 16; ++it) {
            const int c = c0 + 4 * it;
            float4 v = make_float4(f0[c], f1[c], f2[c], f3[c]);
            __stcs(dst, v);
            dst += step;
        }
    } else {
        // Statistically-never slow path (tile with >SLOT_CAP occupied px).
        #pragma unroll 4
        for (int it = 0; it < 16; ++it) {
            const int c = c0 + 4 * it;
            float4 v;
            v.x = (s0 >= 0) ? s_feat[s0 * 65 + c]
                : (s0 == -1) ? 0.0f : featb[(size_t)(-s0 - 2) * C + c];
            v.y = (s1 >= 0) ? s_feat[s1 * 65 + c]
                : (s1 == -1) ? 0.0f : featb[(size_t)(-s1 - 2) * C + c];
            v.z = (s2 >= 0) ? s_feat[s2 * 65 + c]
                : (s2 == -1) ? 0.0f : featb[(size_t)(-s2 - 2) * C + c];
            v.w = (s3 >= 0) ? s_feat[s3 * 65 + c]
                : (s3 == -1) ? 0.0f : featb[(size_t)(-s3 - 2) * C + c];
            __stcs(dst, v);
            dst += step;
        }
    }
}

extern "C" void kernel_launch(void* const* d_in, const int* in_sizes, int n_in,
                              void* d_out, int out_size) {
    const float* feat   = (const float*)d_in[0];   // [B, P, C] fp32
    const int*   coords = (const int*)d_in[1];     // [B, P, 4] int32
    float* out = (float*)d_out;                    // [B, C, H, W] fp32

    scatter_winner_kernel<<<(B * P + 255) / 256, 256>>>(coords);

    dim3 grid(W / TILE_X, H, B);   // 8192 blocks
    gather_out_kernel<<<grid, 128>>>(feat, out);
}

// round 14
// speedup vs baseline: 1.2493x; 1.1955x over previous
#include <cuda_runtime.h>
#include <cuda_bf16.h>

// Problem constants
#define B 4
#define P 12000
#define C 64
#define H 512
#define W 512
#define TILE_X 128
#define SLOT_CAP 20   // staged rows per 128-px tile (mean occ 5.9, +6 sigma)

// Winner pillar map per output pixel, encoded as (p+1); 0 = empty.
// Zero-initialized at module load; gather kernel restores its strip to 0
// (read-then-clear by the SAME thread => ordered), so the all-zeros
// invariant holds before every kernel_launch call / graph replay.
__device__ int g_winner[B * H * W];

// Kernel 1: one thread per (b, p). Reference semantics: sequential .at[].set
// means the LARGEST pillar index wins per pixel -> atomicMax on (p+1).
__global__ void scatter_winner_kernel(const int* __restrict__ coords) {
    int i = blockIdx.x * blockDim.x + threadIdx.x;   // i = b*P + p
    if (i >= B * P) return;
    int b = i / P;
    int p = i - b * P;
    int4 c4 = reinterpret_cast<const int4*>(coords)[i];  // (batch, y, x, z)
    int y = c4.y;
    int x = c4.z;
    if ((unsigned)x < (unsigned)W && (unsigned)y < (unsigned)H) {
        atomicMax(&g_winner[(b * H + y) * W + x], p + 1);
    }
}

// Kernel 2: one 128-thread block per (b, y, 128-px x-tile). 8192 blocks,
// ~12 resident/SM (regs 40), ~3.5 waves -> prologues of late blocks overlap
// the store streams of early ones. Proven-optimal structure (R2/R5 = 45.4us);
// do NOT cap registers (reg-capping strips emit-loop pipelining, R13 data).
__global__ __launch_bounds__(128) void gather_out_kernel(
    const float* __restrict__ feat, float* __restrict__ out) {
    __shared__ int   s_slot[TILE_X];   // >=0: slot | -1: empty | <=-2: pid=-(s)-2
    __shared__ int   s_pid[SLOT_CAP];
    __shared__ int   s_n;
    __shared__ float s_feat[(SLOT_CAP + 1) * 65];  // +1 zero row; pad 65

    const int b   = blockIdx.z;
    const int y   = blockIdx.y;
    const int x0  = blockIdx.x * TILE_X;
    const int tid = threadIdx.x;

    // --- Phase 1: warp 0 reads + clears the 512-B winner strip and compacts.
    int4* wrow4 = reinterpret_cast<int4*>(g_winner + (b * H + y) * W + x0);
    int4 w4;
    if (tid < TILE_X / 4) w4 = wrow4[tid];
    if (tid == 0) s_n = 0;
    if (tid >= 63 && tid < 128) s_feat[SLOT_CAP * 65 + (tid - 63)] = 0.0f;
    __syncthreads();

    if (tid < TILE_X / 4) {
        wrow4[tid] = make_int4(0, 0, 0, 0);   // same thread as reader
        const int wv[4] = {w4.x, w4.y, w4.z, w4.w};
        #pragma unroll
        for (int j = 0; j < 4; ++j) {
            int s = -1;
            if (wv[j] > 0) {
                int sl = atomicAdd(&s_n, 1);
                if (sl < SLOT_CAP) { s_pid[sl] = wv[j] - 1; s = sl; }
                else               { s = -(wv[j] + 1); }   // pid = -s - 2
            }
            s_slot[tid * 4 + j] = s;
        }
    }
    __syncthreads();

    // --- Phase 2: stage occupied feature rows (coalesced float4 loads).
    const float* featb = feat + (size_t)b * P * C;
    const float4* featb4 = reinterpret_cast<const float4*>(featb);
    const int n_stage = min(s_n, SLOT_CAP);
    for (int i = tid; i < n_stage * (C / 4); i += 128) {
        int sl = i >> 4;          // C/4 == 16
        int q  = i & 15;
        float4 v = __ldg(&featb4[(size_t)s_pid[sl] * (C / 4) + q]);
        float* dst = &s_feat[sl * 65 + q * 4];
        dst[0] = v.x; dst[1] = v.y; dst[2] = v.z; dst[3] = v.w;
    }
    __syncthreads();

    // --- Phase 3: emit. lane = x-quad (32 quads), warp w = channels w+4*it.
    const int lane = tid & 31;
    const int c0   = tid >> 5;           // 0..3
    const int px   = lane * 4;

    const int s0 = s_slot[px + 0];
    const int s1 = s_slot[px + 1];
    const int s2 = s_slot[px + 2];
    const int s3 = s_slot[px + 3];

    float4* dst = reinterpret_cast<float4*>(out)
                + ((size_t)(b * C + c0) * H + y) * (W / 4) + (x0 / 4) + lane;
    const size_t step = (size_t)4 * H * (W / 4);   // c += 4

    if (s_n <= SLOT_CAP) {
        const float* f0 = s_feat + (s0 >= 0 ? s0 : SLOT_CAP) * 65;
        const float* f1 = s_feat + (s1 >= 0 ? s1 : SLOT_CAP) * 65;
        const float* f2 = s_feat + (s2 >= 0 ? s2 : SLOT_CAP) * 65;
        const float* f3 = s_feat + (s3 >= 0 ? s3 : SLOT_CAP) * 65;
        #pragma unroll 8
        for (int it = 0; it < 16; ++it) {
            const int c = c0 + 4 * it;
            float4 v = make_float4(f0[c], f1[c], f2[c], f3[c]);
            __stcs(dst, v);
            dst += step;
        }
    } else {
        // Statistically-never slow path (tile with >SLOT_CAP occupied px).
        #pragma unroll 4
        for (int it = 0; it < 16; ++it) {
            const int c = c0 + 4 * it;
            float4 v;
            v.x = (s0 >= 0) ? s_feat[s0 * 65 + c]
                : (s0 == -1) ? 0.0f : featb[(size_t)(-s0 - 2) * C + c];
            v.y = (s1 >= 0) ? s_feat[s1 * 65 + c]
                : (s1 == -1) ? 0.0f : featb[(size_t)(-s1 - 2) * C + c];
            v.z = (s2 >= 0) ? s_feat[s2 * 65 + c]
                : (s2 == -1) ? 0.0f : featb[(size_t)(-s2 - 2) * C + c];
            v.w = (s3 >= 0) ? s_feat[s3 * 65 + c]
                : (s3 == -1) ? 0.0f : featb[(size_t)(-s3 - 2) * C + c];
            __stcs(dst, v);
            dst += step;
        }
    }
}

extern "C" void kernel_launch(void* const* d_in, const int* in_sizes, int n_in,
                              void* d_out, int out_size) {
    const float* feat   = (const float*)d_in[0];   // [B, P, C] fp32
    const int*   coords = (const int*)d_in[1];     // [B, P, 4] int32
    float* out = (float*)d_out;                    // [B, C, H, W] fp32

    scatter_winner_kernel<<<(B * P + 127) / 128, 128>>>(coords);

    dim3 grid(W / TILE_X, H, B);   // 8192 blocks
    gather_out_kernel<<<grid, 128>>>(feat, out);
}

// round 15
// speedup vs baseline: 1.2502x; 1.0007x over previous
#include <cuda_runtime.h>
#include <cuda_bf16.h>

// Problem constants
#define B 4
#define P 12000
#define C 64
#define H 512
#define W 512
#define TILE_X 128
#define SLOT_CAP 20   // staged rows per 128-px tile (mean occ 5.9, +6 sigma)

// Winner pillar map per output pixel, encoded as (p+1); 0 = empty.
// Zero-initialized at module load; gather kernel restores its strip to 0
// (read-then-clear by the SAME thread => ordered), so the all-zeros
// invariant holds before every kernel_launch call / graph replay.
__device__ int g_winner[B * H * W];

// Kernel 1: one thread per (b, p). Reference semantics: sequential .at[].set
// means the LARGEST pillar index wins per pixel -> atomicMax on (p+1).
__global__ void scatter_winner_kernel(const int* __restrict__ coords) {
    int i = blockIdx.x * blockDim.x + threadIdx.x;   // i = b*P + p
    if (i >= B * P) return;
    int b = i / P;
    int p = i - b * P;
    int4 c4 = reinterpret_cast<const int4*>(coords)[i];  // (batch, y, x, z)
    int y = c4.y;
    int x = c4.z;
    if ((unsigned)x < (unsigned)W && (unsigned)y < (unsigned)H) {
        atomicMax(&g_winner[(b * H + y) * W + x], p + 1);
    }
}

// Kernel 2: one 128-thread block per (b, y, 128-px x-tile). 8192 blocks,
// ~12 resident/SM, ~3.5 waves -> prologues of late blocks overlap the store
// streams of early ones (proven-optimal geometry, R2/R5/R14 = 45.2-45.4us).
// R15 change: emit loop drives TWO independent channel half-planes per
// thread (c and c+32) -> 2 independent STG.128 chains, double store MLP.
__global__ __launch_bounds__(128) void gather_out_kernel(
    const float* __restrict__ feat, float* __restrict__ out) {
    __shared__ int   s_slot[TILE_X];   // >=0: slot | -1: empty | <=-2: pid=-(s)-2
    __shared__ int   s_pid[SLOT_CAP];
    __shared__ int   s_n;
    __shared__ float s_feat[(SLOT_CAP + 1) * 65];  // +1 zero row; pad 65

    const int b   = blockIdx.z;
    const int y   = blockIdx.y;
    const int x0  = blockIdx.x * TILE_X;
    const int tid = threadIdx.x;

    // --- Phase 1: warp 0 reads + clears the 512-B winner strip and compacts.
    int4* wrow4 = reinterpret_cast<int4*>(g_winner + (b * H + y) * W + x0);
    int4 w4;
    if (tid < TILE_X / 4) w4 = wrow4[tid];
    if (tid == 0) s_n = 0;
    if (tid >= 63 && tid < 128) s_feat[SLOT_CAP * 65 + (tid - 63)] = 0.0f;
    __syncthreads();

    if (tid < TILE_X / 4) {
        wrow4[tid] = make_int4(0, 0, 0, 0);   // same thread as reader
        const int wv[4] = {w4.x, w4.y, w4.z, w4.w};
        #pragma unroll
        for (int j = 0; j < 4; ++j) {
            int s = -1;
            if (wv[j] > 0) {
                int sl = atomicAdd(&s_n, 1);
                if (sl < SLOT_CAP) { s_pid[sl] = wv[j] - 1; s = sl; }
                else               { s = -(wv[j] + 1); }   // pid = -s - 2
            }
            s_slot[tid * 4 + j] = s;
        }
    }
    __syncthreads();

    // --- Phase 2: stage occupied feature rows (coalesced float4 loads).
    const float* featb = feat + (size_t)b * P * C;
    const float4* featb4 = reinterpret_cast<const float4*>(featb);
    const int n_stage = min(s_n, SLOT_CAP);
    for (int i = tid; i < n_stage * (C / 4); i += 128) {
        int sl = i >> 4;          // C/4 == 16
        int q  = i & 15;
        float4 v = __ldg(&featb4[(size_t)s_pid[sl] * (C / 4) + q]);
        float* dst = &s_feat[sl * 65 + q * 4];
        dst[0] = v.x; dst[1] = v.y; dst[2] = v.z; dst[3] = v.w;
    }
    __syncthreads();

    // --- Phase 3: emit. lane = x-quad, warp w covers channels {w+4i, w+4i+32}.
    const int lane = tid & 31;
    const int c0   = tid >> 5;           // 0..3
    const int px   = lane * 4;

    const int s0 = s_slot[px + 0];
    const int s1 = s_slot[px + 1];
    const int s2 = s_slot[px + 2];
    const int s3 = s_slot[px + 3];

    float4* dstA = reinterpret_cast<float4*>(out)
                 + ((size_t)(b * C + c0) * H + y) * (W / 4) + (x0 / 4) + lane;
    float4* dstB = dstA + (size_t)32 * H * (W / 4);       // channel c0+32
    const size_t step = (size_t)4 * H * (W / 4);          // c += 4

    if (s_n <= SLOT_CAP) {
        const float* f0 = s_feat + (s0 >= 0 ? s0 : SLOT_CAP) * 65;
        const float* f1 = s_feat + (s1 >= 0 ? s1 : SLOT_CAP) * 65;
        const float* f2 = s_feat + (s2 >= 0 ? s2 : SLOT_CAP) * 65;
        const float* f3 = s_feat + (s3 >= 0 ? s3 : SLOT_CAP) * 65;
        #pragma unroll 8
        for (int it = 0; it < 8; ++it) {
            const int ca = c0 + 4 * it;         // 0..31 half
            const int cb = ca + 32;             // 32..63 half
            float4 va = make_float4(f0[ca], f1[ca], f2[ca], f3[ca]);
            float4 vb = make_float4(f0[cb], f1[cb], f2[cb], f3[cb]);
            __stcs(dstA, va);
            __stcs(dstB, vb);
            dstA += step;
            dstB += step;
        }
    } else {
        // Statistically-never slow path (tile with >SLOT_CAP occupied px).
        #pragma unroll 4
        for (int it = 0; it < 16; ++it) {
            const int c = c0 + 4 * it;
            float4 v;
            v.x = (s0 >= 0) ? s_feat[s0 * 65 + c]
                : (s0 == -1) ? 0.0f : featb[(size_t)(-s0 - 2) * C + c];
            v.y = (s1 >= 0) ? s_feat[s1 * 65 + c]
                : (s1 == -1) ? 0.0f : featb[(size_t)(-s1 - 2) * C + c];
            v.z = (s2 >= 0) ? s_feat[s2 * 65 + c]
                : (s2 == -1) ? 0.0f : featb[(size_t)(-s2 - 2) * C + c];
            v.w = (s3 >= 0) ? s_feat[s3 * 65 + c]
                : (s3 == -1) ? 0.0f : featb[(size_t)(-s3 - 2) * C + c];
            __stcs(dstA, v);
            dstA += step;
        }
    }
}

extern "C" void kernel_launch(void* const* d_in, const int* in_sizes, int n_in,
                              void* d_out, int out_size) {
    const float* feat   = (const float*)d_in[0];   // [B, P, C] fp32
    const int*   coords = (const int*)d_in[1];     // [B, P, 4] int32
    float* out = (float*)d_out;                    // [B, C, H, W] fp32

    scatter_winner_kernel<<<(B * P + 127) / 128, 128>>>(coords);

    dim3 grid(W / TILE_X, H, B);   // 8192 blocks
    gather_out_kernel<<<grid, 128>>>(feat, out);
}